// round 14
// baseline (speedup 1.0000x reference)
#include <cuda_runtime.h>
#include <cuda_fp16.h>
#include <math.h>

#define NN 4096
#define DD 64
#define BIGF 1e30f
#define NWARP 64           // 64 strips of 64 columns, 1 warp each
#define TS2 2080           // 2047+31 = 2078 last active step; 130 chunks of 16
#define FULLM 0xffffffffu

// Row-pair diagonal cost storage: g_costd2[((w*TS2)+s)*32 + lane] is a uint2:
//   .x = half2( c[r][c0],   c[r][c1]   )
//   .y = half2( c[r+1][c0], c[r+1][c1] )
// for r = 2*(s - lane), c0 = w*64 + 2*lane.
__device__ uint2  g_costd2[(size_t)NWARP * TS2 * 32];      // ~34 MB
__device__ float  g_nx[NN];
__device__ float  g_ny[NN];
__device__ float  g_c00;                     // c[0][0] for the virtual corner
__device__ __align__(256) float g_bnd[NWARP * NN];   // right-col boundary per strip
__device__ int    g_flag[NWARP];             // rows published per strip

// predicated 8B vector store — no BSSY/BSYNC
__device__ __forceinline__ void st_pred2(float* p, float a, float b, int pred) {
    asm volatile("{ .reg .pred p0; setp.ne.s32 p0, %3, 0; @p0 st.global.v2.f32 [%0], {%1,%2}; }"
                 :: "l"(p), "f"(a), "f"(b), "r"(pred));
}

// ---------------------------------------------------------------------------
__global__ void reset_kernel() {
    if (threadIdx.x < NWARP) g_flag[threadIdx.x] = 0;
}

// ---------------------------------------------------------------------------
__global__ void norms_kernel(const float* __restrict__ x, const float* __restrict__ y) {
    int i = blockIdx.x * blockDim.x + threadIdx.x;
    if (i < NN) {
        const float* p = x + (size_t)i * DD;
        float s = 0.f;
        #pragma unroll
        for (int k = 0; k < DD; k++) s += p[k] * p[k];
        g_nx[i] = s;
    } else if (i < 2 * NN) {
        int j = i - NN;
        const float* p = y + (size_t)j * DD;
        float s = 0.f;
        #pragma unroll
        for (int k = 0; k < DD; k++) s += p[k] * p[k];
        g_ny[j] = s;
    }
}

// ---------------------------------------------------------------------------
// Cost matrix: 64x64 tile per block (tile == strip width), 64 threads,
// 8x8 per thread. Written directly in row-pair diagonal layout.
// ---------------------------------------------------------------------------
__global__ void __launch_bounds__(64) cost_kernel(const float* __restrict__ x,
                                                  const float* __restrict__ y) {
    __shared__ float xs[64][65];
    __shared__ float ys[64][65];

    const int I0 = blockIdx.y * 64;
    const int w  = blockIdx.x;          // strip id == column tile id
    const int J0 = w * 64;
    const int tid = threadIdx.x;        // 0..63

    #pragma unroll 4
    for (int it = 0; it < 16; it++) {               // 16*64 float4 = 4096 floats
        int idx = (it * 64 + tid) * 4;
        int r = idx >> 6, k = idx & 63;
        float4 vx = *(const float4*)(x + (size_t)(I0 + r) * DD + k);
        float4 vy = *(const float4*)(y + (size_t)(J0 + r) * DD + k);
        xs[r][k] = vx.x; xs[r][k+1] = vx.y; xs[r][k+2] = vx.z; xs[r][k+3] = vx.w;
        ys[r][k] = vy.x; ys[r][k+1] = vy.y; ys[r][k+2] = vy.z; ys[r][k+3] = vy.w;
    }
    __syncthreads();

    const int tx = tid & 7, ty = tid >> 3;
    const int r0 = ty * 8, c0 = tx * 8;

    float acc[8][8];
    #pragma unroll
    for (int a = 0; a < 8; a++)
        #pragma unroll
        for (int b = 0; b < 8; b++) acc[a][b] = 0.f;

    #pragma unroll 4
    for (int k = 0; k < DD; k++) {
        float ra[8], rb[8];
        #pragma unroll
        for (int a = 0; a < 8; a++) ra[a] = xs[r0 + a][k];
        #pragma unroll
        for (int b = 0; b < 8; b++) rb[b] = ys[c0 + b][k];
        #pragma unroll
        for (int a = 0; a < 8; a++)
            #pragma unroll
            for (int b = 0; b < 8; b++) acc[a][b] = fmaf(ra[a], rb[b], acc[a][b]);
    }

    float nyv[8];
    #pragma unroll
    for (int b = 0; b < 8; b++) nyv[b] = g_ny[J0 + c0 + b];

    #pragma unroll
    for (int a2 = 0; a2 < 4; a2++) {                // row pairs
        __half2 hp[2][4];
        #pragma unroll
        for (int p = 0; p < 2; p++) {
            const int a = a2 * 2 + p;
            float nx = g_nx[I0 + r0 + a];
            #pragma unroll
            for (int b2 = 0; b2 < 4; b2++) {
                float s0 = nx + nyv[2*b2]   - 2.0f * acc[a][2*b2];
                float s1 = nx + nyv[2*b2+1] - 2.0f * acc[a][2*b2+1];
                float e0 = sqrtf(fmaxf(s0, 1e-12f));
                float e1 = sqrtf(fmaxf(s1, 1e-12f));
                hp[p][b2] = __floats2half2_rn(e0, e1);
            }
        }
        const int i = I0 + r0 + a2 * 2;             // even global row
        #pragma unroll
        for (int b2 = 0; b2 < 4; b2++) {
            const int lane = tx * 4 + b2;           // lane owning these 2 cols
            const size_t s = (size_t)(i >> 1) + lane;
            uint2 pk;
            pk.x = *(unsigned int*)&hp[0][b2];
            pk.y = *(unsigned int*)&hp[1][b2];
            g_costd2[((size_t)w * TS2 + s) * 32 + lane] = pk;
        }
    }

    if (w == 0 && I0 == 0 && tid == 0) {
        float sq = g_nx[0] + g_ny[0] - 2.0f * acc[0][0];   // tid0 owns (0,0)
        g_c00 = sqrtf(fmaxf(sq, 1e-12f));
    }
}

// ---------------------------------------------------------------------------
// Persistent DTW: 64 strips x 1 warp; lane owns 2 cols; at step s computes
// rows r = 2(s-lane), r+1 (4 cells). Left pair via 2 shfls of the neighbor's
// previous (c1-row, c1-row+1) outputs; diag = last step's L1 (register
// rotate). Costs chunk-staged in a 16-step double-buffered register file.
// ---------------------------------------------------------------------------
__global__ void __launch_bounds__(32, 1) dtw_kernel(float* __restrict__ out) {
    const int w = blockIdx.x;
    const int lane = threadIdx.x;
    const uint2* cptr = g_costd2 + (size_t)w * TS2 * 32;

    // t0,t1 = D[r-1][c0], D[r-1][c1]; v01,v11 = my (c1,r), (c1,r+1) to shfl
    float t0 = BIGF, t1 = BIGF, v01 = BIGF, v11 = BIGF, dgTop = BIGF;
    if (w == 0 && lane == 0)
        dgTop = -g_c00;                       // virtual corner seed

    float* bndW = g_bnd + (size_t)w * NN;
    const volatile float* bndp = g_bnd + (size_t)(w > 0 ? w - 1 : 0) * NN;
    const volatile int* vflag = (const volatile int*)&g_flag[w > 0 ? w - 1 : 0];
    int* flagW = &g_flag[w];

    // cost chunk double-buffer: 16 uint2 each (current / next chunk)
    uint2 cpC[16], cpN[16];
    #pragma unroll
    for (int k = 0; k < 16; k++) cpC[k] = cptr[(size_t)k * 32 + lane];
    #pragma unroll
    for (int k = 0; k < 16; k++) cpN[k] = cptr[(size_t)(16 + k) * 32 + lane];

    const bool l0 = (lane == 0);
    const bool l31 = (lane == 31);

    for (int cs = 0; cs < TS2; cs += 16) {
        // chunk poll + boundary rows 2cs..2cs+31 (lane holds row 2cs+lane)
        float bval = BIGF;
        if (w > 0 && 2 * cs < NN) {
            int need = 2 * cs + 32; if (need > NN) need = NN;
            while (*vflag < need) { }
            int bi = 2 * cs + lane; if (bi > NN - 1) bi = NN - 1;
            bval = bndp[bi];
        }

        #pragma unroll
        for (int k = 0; k < 16; k++) {
            const int s = cs + k;
            const int r = 2 * (s - lane);

            float L0 = __shfl_up_sync(FULLM, v01, 1);
            float L1 = __shfl_up_sync(FULLM, v11, 1);
            float b0 = __shfl_sync(FULLM, bval, 2 * k);
            float b1 = __shfl_sync(FULLM, bval, 2 * k + 1);
            if (l0) { L0 = b0; L1 = b1; }     // selects, no branch

            float2 cA = __half22float2(*(const __half2*)&cpC[k].x); // c00,c01
            float2 cB = __half22float2(*(const __half2*)&cpC[k].y); // c10,c11

            // row r
            float n00 = fminf(fminf(fmaf(2.f, cA.x, dgTop), t0 + cA.x), L0  + cA.x);
            float n01 = fminf(fminf(fmaf(2.f, cA.y, t0),    t1 + cA.y), n00 + cA.y);
            // row r+1
            float n10 = fminf(fminf(fmaf(2.f, cB.x, L0),  n00 + cB.x), L1  + cB.x);
            float n11 = fminf(fminf(fmaf(2.f, cB.y, n00), n01 + cB.y), n10 + cB.y);

            const bool act = ((unsigned)r < NN);
            t0  = act ? n10 : t0;
            t1  = act ? n11 : t1;
            v01 = act ? n01 : v01;
            v11 = act ? n11 : v11;
            dgTop = L1;                        // diag for next step

            // boundary store of rows r, r+1 (lane31 only) — predicated 8B
            int rcl = r < 0 ? 0 : (r > NN - 2 ? NN - 2 : r);
            st_pred2(bndW + rcl, n01, n11, (int)(act && l31));
        }

        // rotate buffers; refill cpN with chunk cs+32 (full chunk of slack)
        #pragma unroll
        for (int k = 0; k < 16; k++) cpC[k] = cpN[k];
        if (cs + 32 < TS2) {
            const size_t base = (size_t)(cs + 32) * 32 + lane;
            #pragma unroll
            for (int k = 0; k < 16; k++)
                cpN[k] = cptr[base + (size_t)k * 32];
        }

        // publish: lane31 completed rows 0..2cs-31  =>  flag = 2cs-30
        if (l31) {
            int fv = 2 * cs - 30;
            if (fv > 0) {
                __threadfence();
                atomicExch(flagW, fv);
            }
        }
    }

    if (w == NWARP - 1 && l31)
        out[0] = t1;            // D[4095][4095]
}

// ---------------------------------------------------------------------------
extern "C" void kernel_launch(void* const* d_in, const int* in_sizes, int n_in,
                              void* d_out, int out_size) {
    const float* x = (const float*)d_in[0];
    const float* y = (const float*)d_in[1];
    float* out = (float*)d_out;

    reset_kernel<<<1, 64>>>();
    norms_kernel<<<(2 * NN + 511) / 512, 512>>>(x, y);
    cost_kernel<<<dim3(NN / 64, NN / 64), 64>>>(x, y);
    dtw_kernel<<<NWARP, 32>>>(out);
}